// round 4
// baseline (speedup 1.0000x reference)
#include <cuda_runtime.h>
#include <math.h>

// SpikingLayer T=500, B*N=65536. Hybrid scheme (proven in R3, logic unchanged):
//  - cheap 2nd-order IIR reproduces the 149-tap EPSP conv to ~1e-5 abs error
//  - near-threshold (|u-1| < 1e-3) decisions are recomputed with the reference's
//    exact f32 tap-sum rounding (set history bits, oldest lag first).
// R4 change: software-pipelined double-buffered chunk loads + launch_bounds reg
// budget so all 20 loads of the next chunk are in flight while computing the
// current chunk (R3 was DRAM-latency-bound at regs=40, MLP ~5).

#define TBN 65536
#define T_STEPS 500
#define UF 20          // 500 = 25 chunks * 20
#define NCHUNK 25
#define BLK 64
#define MARGIN 1e-3f

__device__ __forceinline__ void load_chunk(float xv[UF], const float* __restrict__ xp, int c) {
    const float* p = xp + (size_t)c * UF * TBN;
    #pragma unroll
    for (int i = 0; i < UF; i++)
        xv[i] = __ldcs(p + (size_t)i * TBN);
}

__device__ __forceinline__ void process_chunk(
    const float xv[UF], int c, float* __restrict__ op, const float* __restrict__ ks,
    float& v1, float& v2, float& r,
    unsigned& h0, unsigned& h1, unsigned& h2, unsigned& h3, unsigned& h4)
{
    const float c1    = 1.7235681711139413f;    // a + b   (a=e^-0.2, b=e^-0.1)
    const float c2    = -0.7408182206817179f;   // -ab = -e^-0.3
    const float A     = 4.5399929762484854e-05f;// a^50 = b^100 = e^-10
    const float alpha = 0.9048374180359595f;    // e^-0.1

    float* o = op + (size_t)c * UF * TBN;
    #pragma unroll
    for (int i = 0; i < UF; i++) {
        unsigned nb = (xv[i] != 0.0f) ? 1u : 0u;
        h4 = ((h4 << 1) | (h3 >> 31)) & 0x001FFFFFu;
        h3 = (h3 << 1) | (h2 >> 31);
        h2 = (h2 << 1) | (h1 >> 31);
        h1 = (h1 << 1) | (h0 >> 31);
        h0 = (h0 << 1) | nb;

        // IIR approx of the conv (error ~1e-5 << MARGIN)
        float v = fmaf(c1, v1, fmaf(c2, v2, xv[i]));
        v -= (h1 & (1u << 18)) ? A : 0.0f;   // x[t-50]
        v -= (h3 & (1u << 4))  ? A : 0.0f;   // x[t-100]
        v2 = v1; v1 = v;

        float u = v + r;
        if (__builtin_expect(fabsf(u - 1.0f) < MARGIN, 0)) {
            // near threshold: reference's exact f32 rounding — sum ks[j] over
            // set history bits, j descending 148..0, sequential f32 adds.
            float acc = 0.0f;
            unsigned m;
            m = h4; while (m) { unsigned b = 31u - __clz(m); acc += ks[128 + b]; m &= ~(1u << b); }
            m = h3; while (m) { unsigned b = 31u - __clz(m); acc += ks[ 96 + b]; m &= ~(1u << b); }
            m = h2; while (m) { unsigned b = 31u - __clz(m); acc += ks[ 64 + b]; m &= ~(1u << b); }
            m = h1; while (m) { unsigned b = 31u - __clz(m); acc += ks[ 32 + b]; m &= ~(1u << b); }
            m = h0; while (m) { unsigned b = 31u - __clz(m); acc += ks[      b]; m &= ~(1u << b); }
            u = acc + r;
        }

        float s = (u >= 1.0f) ? 1.0f : 0.0f;
        r = (r - s) * alpha;
        __stcs(o + (size_t)i * TBN, s);
    }
}

__global__ __launch_bounds__(BLK, 7)
void SpikingLayer_90202903151092_kernel(const float* __restrict__ x,
                                        const float* __restrict__ ker,
                                        float* __restrict__ out) {
    __shared__ float ks[152];
    for (int i = threadIdx.x; i < 149; i += BLK) ks[i] = ker[i];
    __syncthreads();

    const int idx = blockIdx.x * BLK + threadIdx.x;
    const float* xp = x + idx;
    float*       op = out + idx;

    unsigned h0 = 0u, h1 = 0u, h2 = 0u, h3 = 0u, h4 = 0u;
    float v1 = 0.0f, v2 = 0.0f, r = 0.0f;

    float xa[UF], xb[UF];

    // Software pipeline over 25 chunks: 12 pairs + tail chunk.
    load_chunk(xa, xp, 0);
    #pragma unroll 1
    for (int p = 0; p < 12; p++) {
        const int c0 = 2 * p;
        load_chunk(xb, xp, c0 + 1);                         // prefetch next
        process_chunk(xa, c0, op, ks, v1, v2, r, h0, h1, h2, h3, h4);
        load_chunk(xa, xp, c0 + 2);                         // prefetch next+1
        process_chunk(xb, c0 + 1, op, ks, v1, v2, r, h0, h1, h2, h3, h4);
    }
    process_chunk(xa, 24, op, ks, v1, v2, r, h0, h1, h2, h3, h4);
}

extern "C" void kernel_launch(void* const* d_in, const int* in_sizes, int n_in,
                              void* d_out, int out_size) {
    const float* x   = (const float*)d_in[0];  // binary_input (500,16,1,4096) f32
    const float* ker = (const float*)d_in[1];  // epsp_kernel (1,149) f32
    float* out = (float*)d_out;                // spikes (500,16,4096) f32
    SpikingLayer_90202903151092_kernel<<<TBN / BLK, BLK>>>(x, ker, out);
}